// round 1
// baseline (speedup 1.0000x reference)
#include <cuda_runtime.h>

#define EMB 64
#define NN_MAX 50000

// ---------------- scratch (static device memory; no allocations) ----------------
__device__ __align__(128) float g_h  [NN_MAX * EMB];
__device__ __align__(128) float g_Pa [NN_MAX * EMB];
__device__ __align__(128) float g_Pb [NN_MAX * EMB];
__device__ __align__(128) float g_agg[NN_MAX * EMB];
__device__ __align__(128) float g_u1 [NN_MAX * EMB];
__device__ int g_is64;

// ---------------- detect whether edge_index is int64 or int32 ----------------
// If int64 (values < 50000, positive), the high 32-bit word of every element is 0.
// If int32, those word slots hold actual random indices -> ~never all zero.
__global__ void detect_idx_kernel(const unsigned int* __restrict__ p)
{
    if (threadIdx.x == 0 && blockIdx.x == 0) {
        unsigned int v = 0;
#pragma unroll
        for (int k = 0; k < 64; k++) v |= p[2 * k + 1];
        g_is64 = (v == 0) ? 1 : 0;
    }
}

// ---------------- generic node GEMM: C = act(A1@W1 + A2@W2 + bias) (+resid) ----
// C is M x 64. A_i is M x K_i row-major, W_i is K_i x 64 row-major.
// Block: 64 rows x 64 cols, 256 threads, 4x4 register tile.
template <bool RELU>
__global__ __launch_bounds__(256)
void node_gemm64(const float* __restrict__ A1, const float* __restrict__ W1k, int K1,
                 const float* __restrict__ A2, const float* __restrict__ W2k, int K2,
                 const float* __restrict__ bias, const float* __restrict__ resid,
                 float* __restrict__ C, int M)
{
    __shared__ __align__(16) float sA[16 * 64];   // k-major: sA[k][row]
    __shared__ __align__(16) float sW[16 * 64];   // sW[k][col]

    const int tid  = threadIdx.x;
    const int brow = blockIdx.x * 64;
    const int cg = tid & 15, rg = tid >> 4;
    const int c0 = cg * 4,   r0 = rg * 4;

    float acc[4][4];
#pragma unroll
    for (int i = 0; i < 4; i++)
#pragma unroll
        for (int j = 0; j < 4; j++)
            acc[i][j] = bias ? bias[c0 + j] : 0.0f;

    const int lrow = tid >> 2;          // 0..63 (row this thread stages)
    const int lcol = (tid & 3) * 4;     // 0,4,8,12 (k offset within chunk)
    const int grow = brow + lrow;
    const int kr = tid >> 4;            // 0..15 (W stage row)
    const int wc = (tid & 15) * 4;      // W stage col

#pragma unroll
    for (int p = 0; p < 2; p++) {
        const float* A = p ? A2 : A1;
        const float* W = p ? W2k : W1k;
        const int    K = p ? K2 : K1;
        if (K == 0) continue;
        for (int k0 = 0; k0 < K; k0 += 16) {
            float4 av = make_float4(0.f, 0.f, 0.f, 0.f);
            if (grow < M)
                av = *(const float4*)(A + (long long)grow * K + k0 + lcol);
            sA[(lcol + 0) * 64 + lrow] = av.x;
            sA[(lcol + 1) * 64 + lrow] = av.y;
            sA[(lcol + 2) * 64 + lrow] = av.z;
            sA[(lcol + 3) * 64 + lrow] = av.w;
            *(float4*)&sW[kr * 64 + wc] =
                *(const float4*)(W + (long long)(k0 + kr) * 64 + wc);
            __syncthreads();
#pragma unroll
            for (int kk = 0; kk < 16; kk++) {
                float4 a = *(const float4*)&sA[kk * 64 + r0];
                float4 w = *(const float4*)&sW[kk * 64 + c0];
                float ar[4] = {a.x, a.y, a.z, a.w};
                float wr[4] = {w.x, w.y, w.z, w.w};
#pragma unroll
                for (int i = 0; i < 4; i++)
#pragma unroll
                    for (int j = 0; j < 4; j++)
                        acc[i][j] = fmaf(ar[i], wr[j], acc[i][j]);
            }
            __syncthreads();
        }
    }

#pragma unroll
    for (int i = 0; i < 4; i++) {
        int row = brow + r0 + i;
        if (row < M) {
            float v0 = acc[i][0], v1 = acc[i][1], v2 = acc[i][2], v3 = acc[i][3];
            if (RELU) {
                v0 = fmaxf(v0, 0.f); v1 = fmaxf(v1, 0.f);
                v2 = fmaxf(v2, 0.f); v3 = fmaxf(v3, 0.f);
            }
            if (resid) {
                float4 rr = *(const float4*)(resid + (long long)row * 64 + c0);
                v0 += rr.x; v1 += rr.y; v2 += rr.z; v3 += rr.w;
            }
            *(float4*)(C + (long long)row * 64 + c0) = make_float4(v0, v1, v2, v3);
        }
    }
}

// ---------------- fused edge kernel ------------------------------------------
// Per 64-edge tile:
//   m1 = relu(Pa[dst] + Pb[src] + eattr@W1c)        (b1 already folded into Pa)
//   m2 = relu(m1 @ W2 + b2)
//   agg[dst] += m2   (vectorized L2 reductions)
__global__ __launch_bounds__(256)
void edge_kernel(const void* __restrict__ ei_raw, const float* __restrict__ eattr,
                 const float* __restrict__ Pa, const float* __restrict__ Pb,
                 const float* __restrict__ W1c,   // 6 x 64
                 const float* __restrict__ W2,    // 64 x 64
                 const float* __restrict__ b2,    // 64
                 float* __restrict__ agg, int E)
{
    __shared__ __align__(16) float sM [64 * 64];  // m1, k-major: sM[k][edge]
    __shared__ __align__(16) float sW2[64 * 64];  // sW2[k][col]
    __shared__ float sE[64 * 6];
    __shared__ float sW1c[6 * 64];
    __shared__ float sB2[64];
    __shared__ int   sSrc[64], sDst[64];

    const int tid = threadIdx.x;
    const long long e0 = (long long)blockIdx.x * 64;
    const int is64 = g_is64;

    if (tid < 64) {
        long long eg = e0 + tid;
        int v = 0;
        if (eg < E)
            v = is64 ? (int)((const long long*)ei_raw)[eg]
                     : ((const int*)ei_raw)[eg];
        sSrc[tid] = v;
    } else if (tid < 128) {
        long long eg = e0 + (tid - 64);
        int v = 0;
        if (eg < E)
            v = is64 ? (int)((const long long*)ei_raw)[(long long)E + eg]
                     : ((const int*)ei_raw)[(long long)E + eg];
        sDst[tid - 64] = v;
    }
    for (int i = tid; i < 64 * 6; i += 256) {
        long long eg = e0 + (i / 6);
        sE[i] = (eg < E) ? eattr[e0 * 6 + i] : 0.0f;
    }
    for (int i = tid; i < 6 * 64; i += 256) sW1c[i] = W1c[i];
    if (tid < 64) sB2[tid] = b2[tid];
    {
        const float4* Wv = (const float4*)W2;
        float4* sWv = (float4*)sW2;
        for (int i = tid; i < 64 * 16; i += 256) sWv[i] = Wv[i];
    }
    __syncthreads();

    // ---- phase A: per-edge m1 (each thread: 1 edge, 16 cols) ----
    {
        const int e = tid & 63;
        const int cbase = (tid >> 6) * 16;
        const bool valid = (e0 + e) < E;
        const int d = sDst[e];
        const int s = sSrc[e];
        float v[16];
        if (valid) {
            const float4* pa = (const float4*)(Pa + (long long)d * 64 + cbase);
            const float4* pb = (const float4*)(Pb + (long long)s * 64 + cbase);
#pragma unroll
            for (int u = 0; u < 4; u++) {
                float4 a = pa[u];
                float4 b = pb[u];
                v[4 * u + 0] = a.x + b.x;
                v[4 * u + 1] = a.y + b.y;
                v[4 * u + 2] = a.z + b.z;
                v[4 * u + 3] = a.w + b.w;
            }
            float ea[6];
#pragma unroll
            for (int q = 0; q < 6; q++) ea[q] = sE[e * 6 + q];
#pragma unroll
            for (int q = 0; q < 6; q++)
#pragma unroll
                for (int j = 0; j < 16; j++)
                    v[j] = fmaf(ea[q], sW1c[q * 64 + cbase + j], v[j]);
        } else {
#pragma unroll
            for (int j = 0; j < 16; j++) v[j] = 0.0f;
        }
#pragma unroll
        for (int j = 0; j < 16; j++)
            sM[(cbase + j) * 64 + e] = fmaxf(v[j], 0.0f);
    }
    __syncthreads();

    // ---- phase B: m2 = relu(m1 @ W2 + b2), 4x4 register tile ----
    const int cg = tid & 15, rg = tid >> 4;
    const int c0 = cg * 4,   r0 = rg * 4;
    float acc[4][4];
#pragma unroll
    for (int i = 0; i < 4; i++)
#pragma unroll
        for (int j = 0; j < 4; j++)
            acc[i][j] = sB2[c0 + j];

#pragma unroll 16
    for (int kk = 0; kk < 64; kk++) {
        float4 a = *(const float4*)&sM[kk * 64 + r0];
        float4 w = *(const float4*)&sW2[kk * 64 + c0];
        float ar[4] = {a.x, a.y, a.z, a.w};
        float wr[4] = {w.x, w.y, w.z, w.w};
#pragma unroll
        for (int i = 0; i < 4; i++)
#pragma unroll
            for (int j = 0; j < 4; j++)
                acc[i][j] = fmaf(ar[i], wr[j], acc[i][j]);
    }

    // ---- phase C: scatter-add to agg[dst] with vectorized reductions ----
#pragma unroll
    for (int i = 0; i < 4; i++) {
        const int e = r0 + i;
        if (e0 + e < E) {
            const int d = sDst[e];
            float* p = agg + (long long)d * 64 + c0;
            float x0 = fmaxf(acc[i][0], 0.f);
            float x1 = fmaxf(acc[i][1], 0.f);
            float x2 = fmaxf(acc[i][2], 0.f);
            float x3 = fmaxf(acc[i][3], 0.f);
            asm volatile("red.global.add.v4.f32 [%0], {%1, %2, %3, %4};"
                         :: "l"(p), "f"(x0), "f"(x1), "f"(x2), "f"(x3)
                         : "memory");
        }
    }
}

// ---------------- prediction head: out = (sum_rows h) @ pred_w + M*pred_b -----
__global__ __launch_bounds__(256)
void pred_kernel(const float* __restrict__ h, const float* __restrict__ pw,
                 const float* __restrict__ pb, float* __restrict__ out, int M)
{
    __shared__ float spw[64];
    __shared__ float swarp[8];
    if (threadIdx.x < 64) spw[threadIdx.x] = pw[threadIdx.x];
    __syncthreads();

    float sum = 0.0f;
    for (long long row = (long long)blockIdx.x * blockDim.x + threadIdx.x; row < M;
         row += (long long)gridDim.x * blockDim.x) {
        const float4* hr = (const float4*)(h + row * 64);
#pragma unroll
        for (int u = 0; u < 16; u++) {
            float4 v = hr[u];
            sum = fmaf(v.x, spw[4 * u + 0], sum);
            sum = fmaf(v.y, spw[4 * u + 1], sum);
            sum = fmaf(v.z, spw[4 * u + 2], sum);
            sum = fmaf(v.w, spw[4 * u + 3], sum);
        }
    }
#pragma unroll
    for (int o = 16; o > 0; o >>= 1) sum += __shfl_down_sync(0xffffffffu, sum, o);
    if ((threadIdx.x & 31) == 0) swarp[threadIdx.x >> 5] = sum;
    __syncthreads();
    if (threadIdx.x < 8) {
        float s = swarp[threadIdx.x];
#pragma unroll
        for (int o = 4; o > 0; o >>= 1) s += __shfl_down_sync(0xffu, s, o);
        if (threadIdx.x == 0) {
            if (blockIdx.x == 0) s = fmaf(pb[0], (float)M, s);
            atomicAdd(out, s);
        }
    }
}

// ---------------- launch ------------------------------------------------------
extern "C" void kernel_launch(void* const* d_in, const int* in_sizes, int n_in,
                              void* d_out, int out_size)
{
    const float* x       = (const float*)d_in[0];
    const void*  ei      = d_in[1];
    const float* eattr   = (const float*)d_in[2];
    const float* lin_w   = (const float*)d_in[3];
    const float* lin_b   = (const float*)d_in[4];
    const float* msg_w1  = (const float*)d_in[5];
    const float* msg_b1  = (const float*)d_in[6];
    const float* msg_w2  = (const float*)d_in[7];
    const float* msg_b2  = (const float*)d_in[8];
    const float* upd_w1  = (const float*)d_in[9];
    const float* upd_b1  = (const float*)d_in[10];
    const float* upd_w2  = (const float*)d_in[11];
    const float* upd_b2  = (const float*)d_in[12];
    const float* pred_w  = (const float*)d_in[13];
    const float* pred_b  = (const float*)d_in[14];

    const int M = in_sizes[0] / 128;   // 50000
    const int E = in_sizes[2] / 6;     // 800000 (dtype-independent)

    float *h, *Pa, *Pb, *agg, *u1;
    cudaGetSymbolAddress((void**)&h,   g_h);
    cudaGetSymbolAddress((void**)&Pa,  g_Pa);
    cudaGetSymbolAddress((void**)&Pb,  g_Pb);
    cudaGetSymbolAddress((void**)&agg, g_agg);
    cudaGetSymbolAddress((void**)&u1,  g_u1);

    const int gN = (M + 63) / 64;
    const int gE = (E + 63) / 64;

    detect_idx_kernel<<<1, 32>>>((const unsigned int*)ei);

    // input projection (no relu)
    node_gemm64<false><<<gN, 256>>>(x, lin_w, 128, nullptr, nullptr, 0,
                                    lin_b, nullptr, h, M);

    for (int l = 0; l < 4; l++) {
        const float* W1 = msg_w1 + (size_t)l * 134 * 64;
        // Pa = h @ W1[0:64]   + b1 (dst part; bias folded here)
        node_gemm64<false><<<gN, 256>>>(h, W1, 64, nullptr, nullptr, 0,
                                        msg_b1 + l * 64, nullptr, Pa, M);
        // Pb = h @ W1[64:128]      (src part)
        node_gemm64<false><<<gN, 256>>>(h, W1 + 64 * 64, 64, nullptr, nullptr, 0,
                                        nullptr, nullptr, Pb, M);
        cudaMemsetAsync(agg, 0, (size_t)M * 64 * sizeof(float));
        edge_kernel<<<gE, 256>>>(ei, eattr, Pa, Pb,
                                 W1 + 128 * 64,
                                 msg_w2 + (size_t)l * 64 * 64,
                                 msg_b2 + l * 64, agg, E);
        // u1 = relu(h @ U1a + agg @ U1b + b)
        node_gemm64<true><<<gN, 256>>>(h, upd_w1 + (size_t)l * 128 * 64, 64,
                                       agg, upd_w1 + (size_t)l * 128 * 64 + 64 * 64, 64,
                                       upd_b1 + l * 64, nullptr, u1, M);
        // h = h + relu(u1 @ U2 + b)
        node_gemm64<true><<<gN, 256>>>(u1, upd_w2 + (size_t)l * 64 * 64, 64,
                                       nullptr, nullptr, 0,
                                       upd_b2 + l * 64, h, h, M);
    }

    cudaMemsetAsync(d_out, 0, sizeof(float));
    pred_kernel<<<256, 256>>>(h, pred_w, pred_b, (float*)d_out, M);
}

// round 3
// speedup vs baseline: 1.3472x; 1.3472x over previous
#include <cuda_runtime.h>
#include <cstdint>

#define EMB 64
#define NN_MAX 50000

// ---------------- scratch (static device memory; no allocations) ----------------
__device__ __align__(128) float g_h  [NN_MAX * EMB];
__device__ __align__(128) float g_Pa [NN_MAX * EMB];
__device__ __align__(128) float g_Pb [NN_MAX * EMB];
__device__ __align__(128) float g_agg[NN_MAX * EMB];
__device__ __align__(128) float g_u1 [NN_MAX * EMB];
__device__ int g_is64;

// ---------------- helpers ------------------------------------------------------
__device__ __forceinline__ uint32_t f32_to_tf32(float f) {
    uint32_t u;
    asm("cvt.rna.tf32.f32 %0, %1;" : "=r"(u) : "f"(f));
    return u;
}
// D += A(16x8 tf32) * B(8x8 tf32)
__device__ __forceinline__ void mma_tf32(float* c, const uint32_t* a, const uint32_t* b) {
    asm volatile(
        "mma.sync.aligned.m16n8k8.row.col.f32.tf32.tf32.f32 "
        "{%0,%1,%2,%3}, {%4,%5,%6,%7}, {%8,%9}, {%0,%1,%2,%3};"
        : "+f"(c[0]), "+f"(c[1]), "+f"(c[2]), "+f"(c[3])
        : "r"(a[0]), "r"(a[1]), "r"(a[2]), "r"(a[3]), "r"(b[0]), "r"(b[1]));
}

// ---------------- detect whether edge_index is int64 or int32 ----------------
__global__ void detect_idx_kernel(const unsigned int* __restrict__ p)
{
    if (threadIdx.x == 0 && blockIdx.x == 0) {
        unsigned int v = 0;
#pragma unroll
        for (int k = 0; k < 64; k++) v |= p[2 * k + 1];
        g_is64 = (v == 0) ? 1 : 0;
    }
}

// ---------------- generic node GEMM (known good from R1) -----------------------
template <bool RELU>
__global__ __launch_bounds__(256)
void node_gemm64(const float* __restrict__ A1, const float* __restrict__ W1k, int K1,
                 const float* __restrict__ A2, const float* __restrict__ W2k, int K2,
                 const float* __restrict__ bias, const float* __restrict__ resid,
                 float* __restrict__ C, int M)
{
    __shared__ __align__(16) float sA[16 * 64];
    __shared__ __align__(16) float sW[16 * 64];

    const int tid  = threadIdx.x;
    const int brow = blockIdx.x * 64;
    const int cg = tid & 15, rg = tid >> 4;
    const int c0 = cg * 4,   r0 = rg * 4;

    float acc[4][4];
#pragma unroll
    for (int i = 0; i < 4; i++)
#pragma unroll
        for (int j = 0; j < 4; j++)
            acc[i][j] = bias ? bias[c0 + j] : 0.0f;

    const int lrow = tid >> 2;
    const int lcol = (tid & 3) * 4;
    const int grow = brow + lrow;
    const int kr = tid >> 4;
    const int wc = (tid & 15) * 4;

#pragma unroll
    for (int p = 0; p < 2; p++) {
        const float* A = p ? A2 : A1;
        const float* W = p ? W2k : W1k;
        const int    K = p ? K2 : K1;
        if (K == 0) continue;
        for (int k0 = 0; k0 < K; k0 += 16) {
            float4 av = make_float4(0.f, 0.f, 0.f, 0.f);
            if (grow < M)
                av = *(const float4*)(A + (long long)grow * K + k0 + lcol);
            sA[(lcol + 0) * 64 + lrow] = av.x;
            sA[(lcol + 1) * 64 + lrow] = av.y;
            sA[(lcol + 2) * 64 + lrow] = av.z;
            sA[(lcol + 3) * 64 + lrow] = av.w;
            *(float4*)&sW[kr * 64 + wc] =
                *(const float4*)(W + (long long)(k0 + kr) * 64 + wc);
            __syncthreads();
#pragma unroll
            for (int kk = 0; kk < 16; kk++) {
                float4 a = *(const float4*)&sA[kk * 64 + r0];
                float4 w = *(const float4*)&sW[kk * 64 + c0];
                float ar[4] = {a.x, a.y, a.z, a.w};
                float wr[4] = {w.x, w.y, w.z, w.w};
#pragma unroll
                for (int i = 0; i < 4; i++)
#pragma unroll
                    for (int j = 0; j < 4; j++)
                        acc[i][j] = fmaf(ar[i], wr[j], acc[i][j]);
            }
            __syncthreads();
        }
    }

#pragma unroll
    for (int i = 0; i < 4; i++) {
        int row = brow + r0 + i;
        if (row < M) {
            float v0 = acc[i][0], v1 = acc[i][1], v2 = acc[i][2], v3 = acc[i][3];
            if (RELU) {
                v0 = fmaxf(v0, 0.f); v1 = fmaxf(v1, 0.f);
                v2 = fmaxf(v2, 0.f); v3 = fmaxf(v3, 0.f);
            }
            if (resid) {
                float4 rr = *(const float4*)(resid + (long long)row * 64 + c0);
                v0 += rr.x; v1 += rr.y; v2 += rr.z; v3 += rr.w;
            }
            *(float4*)(C + (long long)row * 64 + c0) = make_float4(v0, v1, v2, v3);
        }
    }
}

// ---------------- edge kernel: tf32 mma.sync, warp-autonomous ------------------
// Per 32-edge chunk per warp:
//   m1 = relu(Pa[dst] + Pb[src] + eattr@W1c)  -> per-warp SMEM tile (tf32)
//   D  = m1(32x64) @ W2(64x64)  via 2x8x8 mma.sync.m16n8k8.tf32
//   agg[dst] += relu(D + b2)    via red.global.add.v2.f32
#define A_STRIDE 68
#define W_STRIDE 72
__global__ __launch_bounds__(256, 2)
void edge_kernel_mma(const void* __restrict__ ei_raw, const float* __restrict__ eattr,
                     const float* __restrict__ Pa, const float* __restrict__ Pb,
                     const float* __restrict__ W1c,   // 6 x 64
                     const float* __restrict__ W2,    // 64 x 64 (k x n)
                     const float* __restrict__ b2,    // 64
                     float* __restrict__ agg, int E)
{
    extern __shared__ __align__(16) char smem[];
    uint32_t* sA   = (uint32_t*)smem;                       // 8 warps x 32 x 68
    uint32_t* sW2  = (uint32_t*)(smem + 69632);             // 64 x 72 (tf32)
    float*    sW1c = (float*)(smem + 88064);                // 6 x 64
    float*    sB2  = (float*)(smem + 89600);                // 64

    const int tid = threadIdx.x;
    const int w   = tid >> 5;
    const int l   = tid & 31;
    const int is64 = g_is64;

    for (int i = tid; i < 64 * 64; i += 256) {
        int k = i >> 6, n = i & 63;
        sW2[k * W_STRIDE + n] = f32_to_tf32(W2[i]);
    }
    for (int i = tid; i < 384; i += 256) sW1c[i] = W1c[i];
    if (tid < 64) sB2[tid] = b2[tid];
    __syncthreads();

    uint32_t* myA = sA + w * 32 * A_STRIDE;
    const int gw = blockIdx.x * 8 + w;
    const int nW = gridDim.x * 8;
    const int nChunks = (E + 31) >> 5;

    const int lg = l >> 2;   // 0..7
    const int lt = l & 3;    // 0..3

    for (int ch = gw; ch < nChunks; ch += nW) {
        const long long e0 = (long long)ch << 5;
        const long long eg = e0 + l;
        const bool valid = eg < E;

        int src = 0, dst = 0;
        if (valid) {
            if (is64) {
                src = (int)((const long long*)ei_raw)[eg];
                dst = (int)((const long long*)ei_raw)[(long long)E + eg];
            } else {
                src = ((const int*)ei_raw)[eg];
                dst = ((const int*)ei_raw)[(long long)E + eg];
            }
        }
        float ea[6];
        if (valid) {
#pragma unroll
            for (int q = 0; q < 6; q++) ea[q] = eattr[eg * 6 + q];
        }

        // ---- phase A: m1 for own edge, 2 halves of 32 cols ----
#pragma unroll
        for (int half = 0; half < 2; half++) {
            const int c0 = half * 32;
            float v[32];
            if (valid) {
                const float4* pa = (const float4*)(Pa + (long long)dst * 64 + c0);
                const float4* pb = (const float4*)(Pb + (long long)src * 64 + c0);
#pragma unroll
                for (int u = 0; u < 8; u++) {
                    float4 a = pa[u];
                    float4 b = pb[u];
                    v[4 * u + 0] = a.x + b.x;
                    v[4 * u + 1] = a.y + b.y;
                    v[4 * u + 2] = a.z + b.z;
                    v[4 * u + 3] = a.w + b.w;
                }
#pragma unroll
                for (int q = 0; q < 6; q++)
#pragma unroll
                    for (int j = 0; j < 32; j++)
                        v[j] = fmaf(ea[q], sW1c[q * 64 + c0 + j], v[j]);
            } else {
#pragma unroll
                for (int j = 0; j < 32; j++) v[j] = 0.0f;
            }
            uint32_t* dstp = myA + l * A_STRIDE + c0;
#pragma unroll
            for (int u = 0; u < 8; u++) {
                uint32_t r0 = f32_to_tf32(fmaxf(v[4 * u + 0], 0.f));
                uint32_t r1 = f32_to_tf32(fmaxf(v[4 * u + 1], 0.f));
                uint32_t r2 = f32_to_tf32(fmaxf(v[4 * u + 2], 0.f));
                uint32_t r3 = f32_to_tf32(fmaxf(v[4 * u + 3], 0.f));
                *(uint4*)(dstp + 4 * u) = make_uint4(r0, r1, r2, r3);
            }
        }
        __syncwarp();

        // ---- mma: D(32x64) = m1 @ W2 ----
        float acc[2][8][4];
#pragma unroll
        for (int g = 0; g < 2; g++)
#pragma unroll
            for (int j = 0; j < 8; j++)
#pragma unroll
                for (int q = 0; q < 4; q++) acc[g][j][q] = 0.0f;

#pragma unroll
        for (int s = 0; s < 8; s++) {
            const int k0 = 8 * s;
            uint32_t bf[8][2];
#pragma unroll
            for (int j = 0; j < 8; j++) {
                bf[j][0] = sW2[(k0 + lt)     * W_STRIDE + 8 * j + lg];
                bf[j][1] = sW2[(k0 + lt + 4) * W_STRIDE + 8 * j + lg];
            }
            uint32_t af[2][4];
#pragma unroll
            for (int g = 0; g < 2; g++) {
                const uint32_t* base = myA + (16 * g + lg) * A_STRIDE + k0 + lt;
                af[g][0] = base[0];
                af[g][1] = base[8 * A_STRIDE];
                af[g][2] = base[4];
                af[g][3] = base[8 * A_STRIDE + 4];
            }
#pragma unroll
            for (int g = 0; g < 2; g++)
#pragma unroll
                for (int j = 0; j < 8; j++)
                    mma_tf32(acc[g][j], af[g], bf[j]);
        }
        __syncwarp();   // all lanes done reading myA before next chunk overwrites

        // ---- epilogue: +b2, relu, scatter ----
#pragma unroll
        for (int g = 0; g < 2; g++) {
#pragma unroll
            for (int h = 0; h < 2; h++) {
                const int row = 16 * g + lg + 8 * h;
                const int dr = __shfl_sync(0xffffffffu, dst, row);
                const bool rv = (e0 + row) < E;
                float* p = agg + (long long)dr * 64 + 2 * lt;
#pragma unroll
                for (int j = 0; j < 8; j++) {
                    float x0 = fmaxf(acc[g][j][2 * h + 0] + sB2[8 * j + 2 * lt + 0], 0.f);
                    float x1 = fmaxf(acc[g][j][2 * h + 1] + sB2[8 * j + 2 * lt + 1], 0.f);
                    if (rv)
                        asm volatile("red.global.add.v2.f32 [%0], {%1, %2};"
                                     :: "l"(p + 8 * j), "f"(x0), "f"(x1) : "memory");
                }
            }
        }
    }
}

// ---------------- prediction head ---------------------------------------------
__global__ __launch_bounds__(256)
void pred_kernel(const float* __restrict__ h, const float* __restrict__ pw,
                 const float* __restrict__ pb, float* __restrict__ out, int M)
{
    __shared__ float spw[64];
    __shared__ float swarp[8];
    if (threadIdx.x < 64) spw[threadIdx.x] = pw[threadIdx.x];
    __syncthreads();

    float sum = 0.0f;
    for (long long row = (long long)blockIdx.x * blockDim.x + threadIdx.x; row < M;
         row += (long long)gridDim.x * blockDim.x) {
        const float4* hr = (const float4*)(h + row * 64);
#pragma unroll
        for (int u = 0; u < 16; u++) {
            float4 v = hr[u];
            sum = fmaf(v.x, spw[4 * u + 0], sum);
            sum = fmaf(v.y, spw[4 * u + 1], sum);
            sum = fmaf(v.z, spw[4 * u + 2], sum);
            sum = fmaf(v.w, spw[4 * u + 3], sum);
        }
    }
#pragma unroll
    for (int o = 16; o > 0; o >>= 1) sum += __shfl_down_sync(0xffffffffu, sum, o);
    if ((threadIdx.x & 31) == 0) swarp[threadIdx.x >> 5] = sum;
    __syncthreads();
    if (threadIdx.x < 8) {
        float s = swarp[threadIdx.x];
#pragma unroll
        for (int o = 4; o > 0; o >>= 1) s += __shfl_down_sync(0xffu, s, o);
        if (threadIdx.x == 0) {
            if (blockIdx.x == 0) s = fmaf(pb[0], (float)M, s);
            atomicAdd(out, s);
        }
    }
}

// ---------------- launch ------------------------------------------------------
extern "C" void kernel_launch(void* const* d_in, const int* in_sizes, int n_in,
                              void* d_out, int out_size)
{
    const float* x       = (const float*)d_in[0];
    const void*  ei      = d_in[1];
    const float* eattr   = (const float*)d_in[2];
    const float* lin_w   = (const float*)d_in[3];
    const float* lin_b   = (const float*)d_in[4];
    const float* msg_w1  = (const float*)d_in[5];
    const float* msg_b1  = (const float*)d_in[6];
    const float* msg_w2  = (const float*)d_in[7];
    const float* msg_b2  = (const float*)d_in[8];
    const float* upd_w1  = (const float*)d_in[9];
    const float* upd_b1  = (const float*)d_in[10];
    const float* upd_w2  = (const float*)d_in[11];
    const float* upd_b2  = (const float*)d_in[12];
    const float* pred_w  = (const float*)d_in[13];
    const float* pred_b  = (const float*)d_in[14];

    const int M = in_sizes[0] / 128;   // 50000
    const int E = in_sizes[2] / 6;     // 800000

    float *h, *Pa, *Pb, *agg, *u1;
    cudaGetSymbolAddress((void**)&h,   g_h);
    cudaGetSymbolAddress((void**)&Pa,  g_Pa);
    cudaGetSymbolAddress((void**)&Pb,  g_Pb);
    cudaGetSymbolAddress((void**)&agg, g_agg);
    cudaGetSymbolAddress((void**)&u1,  g_u1);

    const int gN = (M + 63) / 64;
    const int DSMEM = 89856;
    static int smem_set = 0;
    if (!smem_set) {
        cudaFuncSetAttribute(edge_kernel_mma,
                             cudaFuncAttributeMaxDynamicSharedMemorySize, DSMEM);
        smem_set = 1;
    }
    const int nChunks = (E + 31) / 32;
    int gEdge = 148 * 2;
    if (gEdge * 8 > nChunks) gEdge = (nChunks + 7) / 8;
    if (gEdge < 1) gEdge = 1;

    detect_idx_kernel<<<1, 32>>>((const unsigned int*)ei);

    node_gemm64<false><<<gN, 256>>>(x, lin_w, 128, nullptr, nullptr, 0,
                                    lin_b, nullptr, h, M);

    for (int l = 0; l < 4; l++) {
        const float* W1 = msg_w1 + (size_t)l * 134 * 64;
        node_gemm64<false><<<gN, 256>>>(h, W1, 64, nullptr, nullptr, 0,
                                        msg_b1 + l * 64, nullptr, Pa, M);
        node_gemm64<false><<<gN, 256>>>(h, W1 + 64 * 64, 64, nullptr, nullptr, 0,
                                        nullptr, nullptr, Pb, M);
        cudaMemsetAsync(agg, 0, (size_t)M * 64 * sizeof(float));
        edge_kernel_mma<<<gEdge, 256, DSMEM>>>(ei, eattr, Pa, Pb,
                                               W1 + 128 * 64,
                                               msg_w2 + (size_t)l * 64 * 64,
                                               msg_b2 + l * 64, agg, E);
        node_gemm64<true><<<gN, 256>>>(h, upd_w1 + (size_t)l * 128 * 64, 64,
                                       agg, upd_w1 + (size_t)l * 128 * 64 + 64 * 64, 64,
                                       upd_b1 + l * 64, nullptr, u1, M);
        node_gemm64<true><<<gN, 256>>>(u1, upd_w2 + (size_t)l * 64 * 64, 64,
                                       nullptr, nullptr, 0,
                                       upd_b2 + l * 64, h, h, M);
    }

    cudaMemsetAsync(d_out, 0, sizeof(float));
    pred_kernel<<<256, 256>>>(h, pred_w, pred_b, (float*)d_out, M);
}

// round 4
// speedup vs baseline: 1.3533x; 1.0045x over previous
#include <cuda_runtime.h>
#include <cstdint>

#define EMB 64
#define NN_MAX 50000

// ---------------- scratch (static device memory; no allocations) ----------------
__device__ __align__(128) float g_h  [NN_MAX * EMB];
__device__ __align__(128) float g_Pab[NN_MAX * 128];   // [Pa | Pb] per node
__device__ __align__(128) float g_agg[NN_MAX * EMB];   // zero-init; invariant: zero at launch entry
__device__ __align__(128) float g_u1 [NN_MAX * EMB];
__device__ int g_is64;

// ---------------- helpers ------------------------------------------------------
__device__ __forceinline__ uint32_t f32_to_tf32(float f) {
    uint32_t u;
    asm("cvt.rna.tf32.f32 %0, %1;" : "=r"(u) : "f"(f));
    return u;
}
__device__ __forceinline__ void mma_tf32(float* c, const uint32_t* a, const uint32_t* b) {
    asm volatile(
        "mma.sync.aligned.m16n8k8.row.col.f32.tf32.tf32.f32 "
        "{%0,%1,%2,%3}, {%4,%5,%6,%7}, {%8,%9}, {%0,%1,%2,%3};"
        : "+f"(c[0]), "+f"(c[1]), "+f"(c[2]), "+f"(c[3])
        : "r"(a[0]), "r"(a[1]), "r"(a[2]), "r"(a[3]), "r"(b[0]), "r"(b[1]));
}

// ---------------- detect whether edge_index is int64 or int32 ----------------
__global__ void detect_idx_kernel(const unsigned int* __restrict__ p)
{
    if (threadIdx.x == 0 && blockIdx.x == 0) {
        unsigned int v = 0;
#pragma unroll
        for (int k = 0; k < 64; k++) v |= p[2 * k + 1];
        g_is64 = (v == 0) ? 1 : 0;
    }
}

// ---------------- generic node GEMM (+ optional zero-after-read of A2) --------
template <bool RELU>
__global__ __launch_bounds__(256)
void node_gemm64(const float* __restrict__ A1, const float* __restrict__ W1k, int K1,
                 const float* A2, const float* __restrict__ W2k, int K2,
                 const float* __restrict__ bias, const float* __restrict__ resid,
                 float* __restrict__ C, int M, float* A2zero)
{
    __shared__ __align__(16) float sA[16 * 64];
    __shared__ __align__(16) float sW[16 * 64];

    const int tid  = threadIdx.x;
    const int brow = blockIdx.x * 64;
    const int cg = tid & 15, rg = tid >> 4;
    const int c0 = cg * 4,   r0 = rg * 4;

    float acc[4][4];
#pragma unroll
    for (int i = 0; i < 4; i++)
#pragma unroll
        for (int j = 0; j < 4; j++)
            acc[i][j] = bias ? bias[c0 + j] : 0.0f;

    const int lrow = tid >> 2;
    const int lcol = (tid & 3) * 4;
    const int grow = brow + lrow;
    const int kr = tid >> 4;
    const int wc = (tid & 15) * 4;

#pragma unroll
    for (int p = 0; p < 2; p++) {
        const float* A = p ? A2 : A1;
        const float* W = p ? W2k : W1k;
        const int    K = p ? K2 : K1;
        if (K == 0) continue;
        for (int k0 = 0; k0 < K; k0 += 16) {
            float4 av = make_float4(0.f, 0.f, 0.f, 0.f);
            if (grow < M) {
                av = *(const float4*)(A + (long long)grow * K + k0 + lcol);
                if (p == 1 && A2zero)
                    *(float4*)(A2zero + (long long)grow * K + k0 + lcol) =
                        make_float4(0.f, 0.f, 0.f, 0.f);
            }
            sA[(lcol + 0) * 64 + lrow] = av.x;
            sA[(lcol + 1) * 64 + lrow] = av.y;
            sA[(lcol + 2) * 64 + lrow] = av.z;
            sA[(lcol + 3) * 64 + lrow] = av.w;
            *(float4*)&sW[kr * 64 + wc] =
                *(const float4*)(W + (long long)(k0 + kr) * 64 + wc);
            __syncthreads();
#pragma unroll
            for (int kk = 0; kk < 16; kk++) {
                float4 a = *(const float4*)&sA[kk * 64 + r0];
                float4 w = *(const float4*)&sW[kk * 64 + c0];
                float ar[4] = {a.x, a.y, a.z, a.w};
                float wr[4] = {w.x, w.y, w.z, w.w};
#pragma unroll
                for (int i = 0; i < 4; i++)
#pragma unroll
                    for (int j = 0; j < 4; j++)
                        acc[i][j] = fmaf(ar[i], wr[j], acc[i][j]);
            }
            __syncthreads();
        }
    }

#pragma unroll
    for (int i = 0; i < 4; i++) {
        int row = brow + r0 + i;
        if (row < M) {
            float v0 = acc[i][0], v1 = acc[i][1], v2 = acc[i][2], v3 = acc[i][3];
            if (RELU) {
                v0 = fmaxf(v0, 0.f); v1 = fmaxf(v1, 0.f);
                v2 = fmaxf(v2, 0.f); v3 = fmaxf(v3, 0.f);
            }
            if (resid) {
                float4 rr = *(const float4*)(resid + (long long)row * 64 + c0);
                v0 += rr.x; v1 += rr.y; v2 += rr.z; v3 += rr.w;
            }
            *(float4*)(C + (long long)row * 64 + c0) = make_float4(v0, v1, v2, v3);
        }
    }
}

// ---------------- dual node GEMM: Pab = [h@W1a + b1 | h@W1b] -------------------
// W1 is the (134 x 64) message W1; rows 0..63 = W1a (dst), rows 64..127 = W1b (src).
__global__ __launch_bounds__(512)
void node_gemm_dual(const float* __restrict__ h, const float* __restrict__ W1,
                    const float* __restrict__ b1, float* __restrict__ Pab, int M)
{
    __shared__ __align__(16) float sA[16 * 64];
    __shared__ __align__(16) float sW[16 * 128];

    const int tid  = threadIdx.x;
    const int brow = blockIdx.x * 64;
    const int cg = tid & 31, rg = tid >> 5;
    const int c0 = cg * 4,   r0 = rg * 4;

    float acc[4][4];
#pragma unroll
    for (int i = 0; i < 4; i++)
#pragma unroll
        for (int j = 0; j < 4; j++)
            acc[i][j] = (c0 < 64) ? b1[c0 + j] : 0.0f;

    const int lrow = tid >> 2;          // 0..63 when tid<256
    const int lcol = (tid & 3) * 4;
    const int grow = brow + lrow;
    const int kr = tid >> 5;            // 0..15
    const int wc = (tid & 31) * 4;      // 0..124

    for (int k0 = 0; k0 < 64; k0 += 16) {
        if (tid < 256) {
            float4 av = make_float4(0.f, 0.f, 0.f, 0.f);
            if (grow < M)
                av = *(const float4*)(h + (long long)grow * 64 + k0 + lcol);
            sA[(lcol + 0) * 64 + lrow] = av.x;
            sA[(lcol + 1) * 64 + lrow] = av.y;
            sA[(lcol + 2) * 64 + lrow] = av.z;
            sA[(lcol + 3) * 64 + lrow] = av.w;
        }
        {
            const float* src = (wc < 64)
                ? (W1 + (long long)(k0 + kr) * 64 + wc)
                : (W1 + (long long)(64 + k0 + kr) * 64 + (wc - 64));
            *(float4*)&sW[kr * 128 + wc] = *(const float4*)src;
        }
        __syncthreads();
#pragma unroll
        for (int kk = 0; kk < 16; kk++) {
            float4 a = *(const float4*)&sA[kk * 64 + r0];
            float4 w = *(const float4*)&sW[kk * 128 + c0];
            float ar[4] = {a.x, a.y, a.z, a.w};
            float wr[4] = {w.x, w.y, w.z, w.w};
#pragma unroll
            for (int i = 0; i < 4; i++)
#pragma unroll
                for (int j = 0; j < 4; j++)
                    acc[i][j] = fmaf(ar[i], wr[j], acc[i][j]);
        }
        __syncthreads();
    }

#pragma unroll
    for (int i = 0; i < 4; i++) {
        int row = brow + r0 + i;
        if (row < M)
            *(float4*)(Pab + (long long)row * 128 + c0) =
                make_float4(acc[i][0], acc[i][1], acc[i][2], acc[i][3]);
    }
}

// ---------------- edge kernel: coalesced gather + tf32 mma + v4 scatter --------
#define A_STRIDE 68
#define W_STRIDE 72
__global__ __launch_bounds__(256, 2)
void edge_kernel_mma(const void* __restrict__ ei_raw, const float* __restrict__ eattr,
                     const float* __restrict__ Pab,
                     const float* __restrict__ W1c,   // 6 x 64
                     const float* __restrict__ W2,    // 64 x 64 (k x n)
                     const float* __restrict__ b2,    // 64
                     float* __restrict__ agg, int E)
{
    extern __shared__ __align__(16) char smem[];
    uint32_t* sA   = (uint32_t*)smem;                       // 8 warps x 32 x 68
    uint32_t* sW2  = (uint32_t*)(smem + 69632);             // 64 x 72 (tf32)
    float*    sW1c = (float*)(smem + 88064);                // 6 x 64
    float*    sB2  = (float*)(smem + 89600);                // 64

    const int tid = threadIdx.x;
    const int w   = tid >> 5;
    const int l   = tid & 31;
    const int is64 = g_is64;

    for (int i = tid; i < 64 * 64; i += 256) {
        int k = i >> 6, n = i & 63;
        sW2[k * W_STRIDE + n] = f32_to_tf32(W2[i]);
    }
    for (int i = tid; i < 384; i += 256) sW1c[i] = W1c[i];
    if (tid < 64) sB2[tid] = b2[tid];
    __syncthreads();

    uint32_t* myA = sA + w * 32 * A_STRIDE;
    float*    myF = (float*)myA;
    const int gw = blockIdx.x * 8 + w;
    const int nW = gridDim.x * 8;
    const int nChunks = (E + 31) >> 5;

    const int lg = l >> 2;       // 0..7 (mma row group)
    const int lt = l & 3;        // 0..3 (mma k/col group)
    const int er = l >> 3;       // 0..3 (gather: edge-in-quad)
    const int c4 = (l & 7) * 4;  // gather col base

    for (int ch = gw; ch < nChunks; ch += nW) {
        const long long e0 = (long long)ch << 5;
        const long long eg = e0 + l;
        const bool valid = eg < E;

        int src = 0, dst = 0;
        float ea[6] = {0.f, 0.f, 0.f, 0.f, 0.f, 0.f};
        if (valid) {
            if (is64) {
                src = (int)((const long long*)ei_raw)[eg];
                dst = (int)((const long long*)ei_raw)[(long long)E + eg];
            } else {
                src = ((const int*)ei_raw)[eg];
                dst = ((const int*)ei_raw)[(long long)E + eg];
            }
#pragma unroll
            for (int q = 0; q < 6; q++) ea[q] = eattr[eg * 6 + q];
        }

        // ---- phase A: m1, coalesced (4 edges x 8 lanes per pass) ----
#pragma unroll
        for (int it = 0; it < 8; it++) {
            const int e = 4 * it + er;
            const int de = __shfl_sync(0xffffffffu, dst, e);
            const int se = __shfl_sync(0xffffffffu, src, e);
            float eq[6];
#pragma unroll
            for (int q = 0; q < 6; q++) eq[q] = __shfl_sync(0xffffffffu, ea[q], e);
            const bool ev = (e0 + e) < E;
            const float* par = Pab + (long long)de * 128;
            const float* pbr = Pab + (long long)se * 128 + 64;
#pragma unroll
            for (int h = 0; h < 2; h++) {
                const int c = c4 + 32 * h;
                float v0 = 0.f, v1 = 0.f, v2 = 0.f, v3 = 0.f;
                if (ev) {
                    float4 a = *(const float4*)(par + c);
                    float4 b = *(const float4*)(pbr + c);
                    v0 = a.x + b.x; v1 = a.y + b.y; v2 = a.z + b.z; v3 = a.w + b.w;
#pragma unroll
                    for (int q = 0; q < 6; q++) {
                        float4 wv = *(const float4*)(sW1c + q * 64 + c);
                        v0 = fmaf(eq[q], wv.x, v0);
                        v1 = fmaf(eq[q], wv.y, v1);
                        v2 = fmaf(eq[q], wv.z, v2);
                        v3 = fmaf(eq[q], wv.w, v3);
                    }
                }
                uint32_t r0 = f32_to_tf32(fmaxf(v0, 0.f));
                uint32_t r1 = f32_to_tf32(fmaxf(v1, 0.f));
                uint32_t r2 = f32_to_tf32(fmaxf(v2, 0.f));
                uint32_t r3 = f32_to_tf32(fmaxf(v3, 0.f));
                *(uint4*)(myA + e * A_STRIDE + c) = make_uint4(r0, r1, r2, r3);
            }
        }
        __syncwarp();

        // ---- mma: D(32x64) = m1 @ W2 ----
        float acc[2][8][4];
#pragma unroll
        for (int g = 0; g < 2; g++)
#pragma unroll
            for (int j = 0; j < 8; j++)
#pragma unroll
                for (int q = 0; q < 4; q++) acc[g][j][q] = 0.0f;

#pragma unroll
        for (int s = 0; s < 8; s++) {
            const int k0 = 8 * s;
            uint32_t bf[8][2];
#pragma unroll
            for (int j = 0; j < 8; j++) {
                bf[j][0] = sW2[(k0 + lt)     * W_STRIDE + 8 * j + lg];
                bf[j][1] = sW2[(k0 + lt + 4) * W_STRIDE + 8 * j + lg];
            }
            uint32_t af[2][4];
#pragma unroll
            for (int g = 0; g < 2; g++) {
                const uint32_t* base = myA + (16 * g + lg) * A_STRIDE + k0 + lt;
                af[g][0] = base[0];
                af[g][1] = base[8 * A_STRIDE];
                af[g][2] = base[4];
                af[g][3] = base[8 * A_STRIDE + 4];
            }
#pragma unroll
            for (int g = 0; g < 2; g++)
#pragma unroll
                for (int j = 0; j < 8; j++)
                    mma_tf32(acc[g][j], af[g], bf[j]);
        }
        __syncwarp();   // all lanes done reading myA (tf32 m1)

        // ---- epilogue: transpose via SMEM, then +b2, relu, red.v4 scatter ----
#pragma unroll
        for (int g = 0; g < 2; g++)
#pragma unroll
            for (int h = 0; h < 2; h++) {
                const int row = 16 * g + 8 * h + lg;
#pragma unroll
                for (int j = 0; j < 8; j++)
                    *(float2*)(myF + row * A_STRIDE + 8 * j + 2 * lt) =
                        make_float2(acc[g][j][2 * h], acc[g][j][2 * h + 1]);
            }
        __syncwarp();

        if (valid) {
            float* p = agg + (long long)dst * 64;
#pragma unroll
            for (int u = 0; u < 16; u++) {
                float4 t  = *(const float4*)(myF + l * A_STRIDE + 4 * u);
                float4 bb = *(const float4*)(sB2 + 4 * u);
                float x0 = fmaxf(t.x + bb.x, 0.f);
                float x1 = fmaxf(t.y + bb.y, 0.f);
                float x2 = fmaxf(t.z + bb.z, 0.f);
                float x3 = fmaxf(t.w + bb.w, 0.f);
                asm volatile("red.global.add.v4.f32 [%0], {%1, %2, %3, %4};"
                             :: "l"(p + 4 * u), "f"(x0), "f"(x1), "f"(x2), "f"(x3)
                             : "memory");
            }
        }
        __syncwarp();   // readers of myF done before next chunk's phase A
    }
}

// ---------------- prediction head ---------------------------------------------
__global__ __launch_bounds__(256)
void pred_kernel(const float* __restrict__ h, const float* __restrict__ pw,
                 const float* __restrict__ pb, float* __restrict__ out, int M)
{
    __shared__ float spw[64];
    __shared__ float swarp[8];
    if (threadIdx.x < 64) spw[threadIdx.x] = pw[threadIdx.x];
    __syncthreads();

    float sum = 0.0f;
    for (long long row = (long long)blockIdx.x * blockDim.x + threadIdx.x; row < M;
         row += (long long)gridDim.x * blockDim.x) {
        const float4* hr = (const float4*)(h + row * 64);
#pragma unroll
        for (int u = 0; u < 16; u++) {
            float4 v = hr[u];
            sum = fmaf(v.x, spw[4 * u + 0], sum);
            sum = fmaf(v.y, spw[4 * u + 1], sum);
            sum = fmaf(v.z, spw[4 * u + 2], sum);
            sum = fmaf(v.w, spw[4 * u + 3], sum);
        }
    }
#pragma unroll
    for (int o = 16; o > 0; o >>= 1) sum += __shfl_down_sync(0xffffffffu, sum, o);
    if ((threadIdx.x & 31) == 0) swarp[threadIdx.x >> 5] = sum;
    __syncthreads();
    if (threadIdx.x < 8) {
        float s = swarp[threadIdx.x];
#pragma unroll
        for (int o = 4; o > 0; o >>= 1) s += __shfl_down_sync(0xffu, s, o);
        if (threadIdx.x == 0) {
            if (blockIdx.x == 0) s = fmaf(pb[0], (float)M, s);
            atomicAdd(out, s);
        }
    }
}

// ---------------- launch ------------------------------------------------------
extern "C" void kernel_launch(void* const* d_in, const int* in_sizes, int n_in,
                              void* d_out, int out_size)
{
    const float* x       = (const float*)d_in[0];
    const void*  ei      = d_in[1];
    const float* eattr   = (const float*)d_in[2];
    const float* lin_w   = (const float*)d_in[3];
    const float* lin_b   = (const float*)d_in[4];
    const float* msg_w1  = (const float*)d_in[5];
    const float* msg_b1  = (const float*)d_in[6];
    const float* msg_w2  = (const float*)d_in[7];
    const float* msg_b2  = (const float*)d_in[8];
    const float* upd_w1  = (const float*)d_in[9];
    const float* upd_b1  = (const float*)d_in[10];
    const float* upd_w2  = (const float*)d_in[11];
    const float* upd_b2  = (const float*)d_in[12];
    const float* pred_w  = (const float*)d_in[13];
    const float* pred_b  = (const float*)d_in[14];

    const int M = in_sizes[0] / 128;   // 50000
    const int E = in_sizes[2] / 6;     // 800000

    float *h, *Pab, *agg, *u1;
    cudaGetSymbolAddress((void**)&h,   g_h);
    cudaGetSymbolAddress((void**)&Pab, g_Pab);
    cudaGetSymbolAddress((void**)&agg, g_agg);
    cudaGetSymbolAddress((void**)&u1,  g_u1);

    const int gN = (M + 63) / 64;
    const int DSMEM = 89856;
    cudaFuncSetAttribute(edge_kernel_mma,
                         cudaFuncAttributeMaxDynamicSharedMemorySize, DSMEM);
    const int nChunks = (E + 31) / 32;
    int gEdge = 148 * 2;
    if (gEdge * 8 > nChunks) gEdge = (nChunks + 7) / 8;
    if (gEdge < 1) gEdge = 1;

    detect_idx_kernel<<<1, 32>>>((const unsigned int*)ei);

    node_gemm64<false><<<gN, 256>>>(x, lin_w, 128, nullptr, nullptr, 0,
                                    lin_b, nullptr, h, M, nullptr);

    for (int l = 0; l < 4; l++) {
        const float* W1 = msg_w1 + (size_t)l * 134 * 64;
        // Pab = [h@W1a + b1 | h@W1b]
        node_gemm_dual<<<gN, 512>>>(h, W1, msg_b1 + l * 64, Pab, M);
        // edge: m2 scatter-add into agg (agg guaranteed zero here)
        edge_kernel_mma<<<gEdge, 256, DSMEM>>>(ei, eattr, Pab,
                                               W1 + 128 * 64,
                                               msg_w2 + (size_t)l * 64 * 64,
                                               msg_b2 + l * 64, agg, E);
        // u1 = relu(h@U1a + agg@U1b + b); zeroes agg after reading it
        node_gemm64<true><<<gN, 256>>>(h, upd_w1 + (size_t)l * 128 * 64, 64,
                                       agg, upd_w1 + (size_t)l * 128 * 64 + 64 * 64, 64,
                                       upd_b1 + l * 64, nullptr, u1, M, agg);
        // h = h + relu(u1@U2 + b)
        node_gemm64<true><<<gN, 256>>>(u1, upd_w2 + (size_t)l * 64 * 64, 64,
                                       nullptr, nullptr, 0,
                                       upd_b2 + l * 64, h, h, M, nullptr);
    }

    cudaMemsetAsync(d_out, 0, sizeof(float));
    pred_kernel<<<256, 256>>>(h, pred_w, pred_b, (float*)d_out, M);
}

// round 5
// speedup vs baseline: 1.4535x; 1.0740x over previous
#include <cuda_runtime.h>
#include <cstdint>

#define EMB 64
#define NN_MAX 50000
#define NSCAN 50176          // 49 * 1024
#define NE_MAX 800000
#define NE_PAD (NE_MAX + 64)

// ---------------- scratch (static device memory; no allocations) ----------------
__device__ __align__(128) float g_h  [NN_MAX * EMB];
__device__ __align__(128) float g_Pab[NN_MAX * 128];   // [Pa | Pb] per node
__device__ __align__(128) float g_agg[NN_MAX * EMB];   // zero at launch entry (invariant)
__device__ int g_is64;

// sort scratch
__device__ int   g_cnt [NSCAN];
__device__ int   g_inc [NSCAN];
__device__ int   g_cur [NSCAN];
__device__ int   g_bsum[64];
__device__ __align__(128) int   g_srcS[NE_PAD];
__device__ __align__(128) int   g_dstS[NE_PAD];
__device__ __align__(128) float g_eaS [NE_PAD * 6];

// ---------------- helpers ------------------------------------------------------
__device__ __forceinline__ uint32_t f32_to_tf32(float f) {
    uint32_t u;
    asm("cvt.rna.tf32.f32 %0, %1;" : "=r"(u) : "f"(f));
    return u;
}
__device__ __forceinline__ void mma_tf32(float* c, const uint32_t* a, const uint32_t* b) {
    asm volatile(
        "mma.sync.aligned.m16n8k8.row.col.f32.tf32.tf32.f32 "
        "{%0,%1,%2,%3}, {%4,%5,%6,%7}, {%8,%9}, {%0,%1,%2,%3};"
        : "+f"(c[0]), "+f"(c[1]), "+f"(c[2]), "+f"(c[3])
        : "r"(a[0]), "r"(a[1]), "r"(a[2]), "r"(a[3]), "r"(b[0]), "r"(b[1]));
}

// ---------------- detect whether edge_index is int64 or int32 ----------------
__global__ void detect_idx_kernel(const unsigned int* __restrict__ p)
{
    if (threadIdx.x == 0 && blockIdx.x == 0) {
        unsigned int v = 0;
#pragma unroll
        for (int k = 0; k < 64; k++) v |= p[2 * k + 1];
        g_is64 = (v == 0) ? 1 : 0;
    }
}

// ---------------- counting sort by dst ----------------------------------------
__global__ void hist_kernel(const void* __restrict__ ei, int E)
{
    const int is64 = g_is64;
    for (long long e = (long long)blockIdx.x * blockDim.x + threadIdx.x; e < E;
         e += (long long)gridDim.x * blockDim.x) {
        int dst = is64 ? (int)((const long long*)ei)[(long long)E + e]
                       : ((const int*)ei)[(long long)E + e];
        atomicAdd(&g_cnt[dst], 1);
    }
}

__global__ __launch_bounds__(1024) void scan1_kernel()
{
    const int t = threadIdx.x, b = blockIdx.x;
    const int i = b * 1024 + t;
    const int lane = t & 31, wid = t >> 5;
    int x = g_cnt[i];
#pragma unroll
    for (int s = 1; s < 32; s <<= 1) {
        int u = __shfl_up_sync(0xffffffffu, x, s);
        if (lane >= s) x += u;
    }
    __shared__ int ws[32];
    if (lane == 31) ws[wid] = x;
    __syncthreads();
    if (wid == 0) {
        int y = ws[lane];
#pragma unroll
        for (int s = 1; s < 32; s <<= 1) {
            int u = __shfl_up_sync(0xffffffffu, y, s);
            if (lane >= s) y += u;
        }
        ws[lane] = y;
    }
    __syncthreads();
    int inc = x + (wid ? ws[wid - 1] : 0);
    g_inc[i] = inc;
    if (t == 1023) g_bsum[b] = inc;
}

__global__ void scan2_kernel(int nb)
{
    if (threadIdx.x == 0 && blockIdx.x == 0) {
        int run = 0;
        for (int b = 0; b < nb; b++) { int t = g_bsum[b]; g_bsum[b] = run; run += t; }
    }
}

__global__ __launch_bounds__(1024) void scan3_kernel()
{
    const int i = blockIdx.x * 1024 + threadIdx.x;
    g_cur[i] = g_inc[i] - g_cnt[i] + g_bsum[blockIdx.x];
}

__global__ void scatter_kernel(const void* __restrict__ ei,
                               const float* __restrict__ eattr, int E)
{
    const int is64 = g_is64;
    for (long long e = (long long)blockIdx.x * blockDim.x + threadIdx.x; e < E;
         e += (long long)gridDim.x * blockDim.x) {
        int src, dst;
        if (is64) {
            src = (int)((const long long*)ei)[e];
            dst = (int)((const long long*)ei)[(long long)E + e];
        } else {
            src = ((const int*)ei)[e];
            dst = ((const int*)ei)[(long long)E + e];
        }
        int pos = atomicAdd(&g_cur[dst], 1);
        g_srcS[pos] = src;
        g_dstS[pos] = dst;
#pragma unroll
        for (int q = 0; q < 6; q++) g_eaS[(long long)pos * 6 + q] = eattr[e * 6 + q];
    }
}

// ---------------- generic node GEMM (input projection) -------------------------
template <bool RELU>
__global__ __launch_bounds__(256)
void node_gemm64(const float* __restrict__ A1, const float* __restrict__ W1k, int K1,
                 const float* __restrict__ bias, float* __restrict__ C, int M)
{
    __shared__ __align__(16) float sA[16 * 64];
    __shared__ __align__(16) float sW[16 * 64];

    const int tid  = threadIdx.x;
    const int brow = blockIdx.x * 64;
    const int cg = tid & 15, rg = tid >> 4;
    const int c0 = cg * 4,   r0 = rg * 4;

    float acc[4][4];
#pragma unroll
    for (int i = 0; i < 4; i++)
#pragma unroll
        for (int j = 0; j < 4; j++)
            acc[i][j] = bias[c0 + j];

    const int lrow = tid >> 2;
    const int lcol = (tid & 3) * 4;
    const int grow = brow + lrow;
    const int kr = tid >> 4;
    const int wc = (tid & 15) * 4;

    for (int k0 = 0; k0 < K1; k0 += 16) {
        float4 av = make_float4(0.f, 0.f, 0.f, 0.f);
        if (grow < M)
            av = *(const float4*)(A1 + (long long)grow * K1 + k0 + lcol);
        sA[(lcol + 0) * 64 + lrow] = av.x;
        sA[(lcol + 1) * 64 + lrow] = av.y;
        sA[(lcol + 2) * 64 + lrow] = av.z;
        sA[(lcol + 3) * 64 + lrow] = av.w;
        *(float4*)&sW[kr * 64 + wc] =
            *(const float4*)(W1k + (long long)(k0 + kr) * 64 + wc);
        __syncthreads();
#pragma unroll
        for (int kk = 0; kk < 16; kk++) {
            float4 a = *(const float4*)&sA[kk * 64 + r0];
            float4 w = *(const float4*)&sW[kk * 64 + c0];
            float ar[4] = {a.x, a.y, a.z, a.w};
            float wr[4] = {w.x, w.y, w.z, w.w};
#pragma unroll
            for (int i = 0; i < 4; i++)
#pragma unroll
                for (int j = 0; j < 4; j++)
                    acc[i][j] = fmaf(ar[i], wr[j], acc[i][j]);
        }
        __syncthreads();
    }

#pragma unroll
    for (int i = 0; i < 4; i++) {
        int row = brow + r0 + i;
        if (row < M) {
            float v0 = acc[i][0], v1 = acc[i][1], v2 = acc[i][2], v3 = acc[i][3];
            if (RELU) {
                v0 = fmaxf(v0, 0.f); v1 = fmaxf(v1, 0.f);
                v2 = fmaxf(v2, 0.f); v3 = fmaxf(v3, 0.f);
            }
            *(float4*)(C + (long long)row * 64 + c0) = make_float4(v0, v1, v2, v3);
        }
    }
}

// ---------------- dual node GEMM: Pab = [h@W1a + b1 | h@W1b] -------------------
__global__ __launch_bounds__(512)
void node_gemm_dual(const float* __restrict__ h, const float* __restrict__ W1,
                    const float* __restrict__ b1, float* __restrict__ Pab, int M)
{
    __shared__ __align__(16) float sA[16 * 64];
    __shared__ __align__(16) float sW[16 * 128];

    const int tid  = threadIdx.x;
    const int brow = blockIdx.x * 64;
    const int cg = tid & 31, rg = tid >> 5;
    const int c0 = cg * 4,   r0 = rg * 4;

    float acc[4][4];
#pragma unroll
    for (int i = 0; i < 4; i++)
#pragma unroll
        for (int j = 0; j < 4; j++)
            acc[i][j] = (c0 < 64) ? b1[c0 + j] : 0.0f;

    const int lrow = tid >> 2;
    const int lcol = (tid & 3) * 4;
    const int grow = brow + lrow;
    const int kr = tid >> 5;
    const int wc = (tid & 31) * 4;

    for (int k0 = 0; k0 < 64; k0 += 16) {
        if (tid < 256) {
            float4 av = make_float4(0.f, 0.f, 0.f, 0.f);
            if (grow < M)
                av = *(const float4*)(h + (long long)grow * 64 + k0 + lcol);
            sA[(lcol + 0) * 64 + lrow] = av.x;
            sA[(lcol + 1) * 64 + lrow] = av.y;
            sA[(lcol + 2) * 64 + lrow] = av.z;
            sA[(lcol + 3) * 64 + lrow] = av.w;
        }
        {
            const float* src = (wc < 64)
                ? (W1 + (long long)(k0 + kr) * 64 + wc)
                : (W1 + (long long)(64 + k0 + kr) * 64 + (wc - 64));
            *(float4*)&sW[kr * 128 + wc] = *(const float4*)src;
        }
        __syncthreads();
#pragma unroll
        for (int kk = 0; kk < 16; kk++) {
            float4 a = *(const float4*)&sA[kk * 64 + r0];
            float4 w = *(const float4*)&sW[kk * 128 + c0];
            float ar[4] = {a.x, a.y, a.z, a.w};
            float wr[4] = {w.x, w.y, w.z, w.w};
#pragma unroll
            for (int i = 0; i < 4; i++)
#pragma unroll
                for (int j = 0; j < 4; j++)
                    acc[i][j] = fmaf(ar[i], wr[j], acc[i][j]);
        }
        __syncthreads();
    }

#pragma unroll
    for (int i = 0; i < 4; i++) {
        int row = brow + r0 + i;
        if (row < M)
            *(float4*)(Pab + (long long)row * 128 + c0) =
                make_float4(acc[i][0], acc[i][1], acc[i][2], acc[i][3]);
    }
}

// ---------------- fused update: h += relu(relu([h|agg]@U1+b1)@U2+b2) ----------
// Also zeroes agg after reading it (restores the launch-entry invariant).
__global__ __launch_bounds__(256)
void fused_update(const float* __restrict__ h_in, const float* __restrict__ U1,
                  const float* __restrict__ b1, const float* __restrict__ U2,
                  const float* __restrict__ b2, float* agg,
                  float* __restrict__ h_out, int M)
{
    __shared__ __align__(16) float sA [16 * 64];
    __shared__ __align__(16) float sW [16 * 64];
    __shared__ __align__(16) float sU1[64 * 68];

    const int tid  = threadIdx.x;
    const int brow = blockIdx.x * 64;
    const int cg = tid & 15, rg = tid >> 4;
    const int c0 = cg * 4,   r0 = rg * 4;

    const int lrow = tid >> 2;
    const int lcol = (tid & 3) * 4;
    const int grow = brow + lrow;
    const int kr = tid >> 4;
    const int wc = (tid & 15) * 4;

    float acc[4][4];
#pragma unroll
    for (int i = 0; i < 4; i++)
#pragma unroll
        for (int j = 0; j < 4; j++)
            acc[i][j] = b1[c0 + j];

#pragma unroll
    for (int p = 0; p < 2; p++) {
        const float* A = p ? agg : h_in;
        const float* W = U1 + (long long)p * 64 * 64;
        for (int k0 = 0; k0 < 64; k0 += 16) {
            float4 av = make_float4(0.f, 0.f, 0.f, 0.f);
            if (grow < M) {
                av = *(const float4*)(A + (long long)grow * 64 + k0 + lcol);
                if (p == 1)
                    *(float4*)(agg + (long long)grow * 64 + k0 + lcol) =
                        make_float4(0.f, 0.f, 0.f, 0.f);
            }
            sA[(lcol + 0) * 64 + lrow] = av.x;
            sA[(lcol + 1) * 64 + lrow] = av.y;
            sA[(lcol + 2) * 64 + lrow] = av.z;
            sA[(lcol + 3) * 64 + lrow] = av.w;
            *(float4*)&sW[kr * 64 + wc] =
                *(const float4*)(W + (long long)(k0 + kr) * 64 + wc);
            __syncthreads();
#pragma unroll
            for (int kk = 0; kk < 16; kk++) {
                float4 a = *(const float4*)&sA[kk * 64 + r0];
                float4 w = *(const float4*)&sW[kk * 64 + c0];
                float ar[4] = {a.x, a.y, a.z, a.w};
                float wr[4] = {w.x, w.y, w.z, w.w};
#pragma unroll
                for (int i = 0; i < 4; i++)
#pragma unroll
                    for (int j = 0; j < 4; j++)
                        acc[i][j] = fmaf(ar[i], wr[j], acc[i][j]);
            }
            __syncthreads();
        }
    }

    // u1 = relu(acc) -> smem, k-major
#pragma unroll
    for (int i = 0; i < 4; i++)
#pragma unroll
        for (int j = 0; j < 4; j++)
            sU1[(c0 + j) * 68 + r0 + i] = fmaxf(acc[i][j], 0.0f);
    __syncthreads();

    // phase 2: acc2 = u1 @ U2 + b2
    float acc2[4][4];
#pragma unroll
    for (int i = 0; i < 4; i++)
#pragma unroll
        for (int j = 0; j < 4; j++)
            acc2[i][j] = b2[c0 + j];

    for (int k0 = 0; k0 < 64; k0 += 16) {
        *(float4*)&sW[kr * 64 + wc] =
            *(const float4*)(U2 + (long long)(k0 + kr) * 64 + wc);
        __syncthreads();
#pragma unroll
        for (int kk = 0; kk < 16; kk++) {
            float4 a = *(const float4*)&sU1[(k0 + kk) * 68 + r0];
            float4 w = *(const float4*)&sW[kk * 64 + c0];
            float ar[4] = {a.x, a.y, a.z, a.w};
            float wr[4] = {w.x, w.y, w.z, w.w};
#pragma unroll
            for (int i = 0; i < 4; i++)
#pragma unroll
                for (int j = 0; j < 4; j++)
                    acc2[i][j] = fmaf(ar[i], wr[j], acc2[i][j]);
        }
        __syncthreads();
    }

#pragma unroll
    for (int i = 0; i < 4; i++) {
        int row = brow + r0 + i;
        if (row < M) {
            float4 hh = *(const float4*)(h_out + (long long)row * 64 + c0);
            hh.x += fmaxf(acc2[i][0], 0.f);
            hh.y += fmaxf(acc2[i][1], 0.f);
            hh.z += fmaxf(acc2[i][2], 0.f);
            hh.w += fmaxf(acc2[i][3], 0.f);
            *(float4*)(h_out + (long long)row * 64 + c0) = hh;
        }
    }
}

// ---------------- edge kernel: sorted edges, tf32 mma, segmented-scan scatter --
#define A_STRIDE 68
#define W_STRIDE 72
__global__ __launch_bounds__(256, 2)
void edge_kernel_mma(const float* __restrict__ Pab,
                     const float* __restrict__ W1c,   // 6 x 64
                     const float* __restrict__ W2,    // 64 x 64 (k x n)
                     const float* __restrict__ b2,    // 64
                     float* __restrict__ agg, int E)
{
    extern __shared__ __align__(16) char smem[];
    uint32_t* sA   = (uint32_t*)smem;                       // 8 warps x 32 x 68
    uint32_t* sW2  = (uint32_t*)(smem + 69632);             // 64 x 72 (tf32)
    float*    sW1c = (float*)(smem + 88064);                // 6 x 64
    float*    sB2  = (float*)(smem + 89600);                // 64
    float*    sEa  = (float*)(smem + 89856);                // 8 warps x 192

    const int tid = threadIdx.x;
    const int w   = tid >> 5;
    const int l   = tid & 31;

    for (int i = tid; i < 64 * 64; i += 256) {
        int k = i >> 6, n = i & 63;
        sW2[k * W_STRIDE + n] = f32_to_tf32(W2[i]);
    }
    for (int i = tid; i < 384; i += 256) sW1c[i] = W1c[i];
    if (tid < 64) sB2[tid] = b2[tid];
    __syncthreads();

    uint32_t* myA  = sA + w * 32 * A_STRIDE;
    float*    myF  = (float*)myA;
    float*    myEa = sEa + w * 192;
    const int gw = blockIdx.x * 8 + w;
    const int nW = gridDim.x * 8;
    const int nChunks = (E + 31) >> 5;

    const int lg = l >> 2;       // 0..7
    const int lt = l & 3;        // 0..3
    const int er = l >> 3;       // 0..3
    const int c4 = (l & 7) * 4;

    unsigned lm_le;
    asm("mov.u32 %0, %%lanemask_le;" : "=r"(lm_le));

    for (int ch = gw; ch < nChunks; ch += nW) {
        const long long e0 = (long long)ch << 5;
        const long long eg = e0 + l;
        const bool valid = eg < E;

        int src = 0, dst = -1;
        if (valid) {
            src = g_srcS[eg];
            dst = g_dstS[eg];
        }
        // stage eattr coalesced (48 float4 per warp)
        {
            const float4* gsrc = (const float4*)(g_eaS + e0 * 6);
            if (l < 16) {
                *(float4*)(myEa + 4 * l)        = gsrc[l];
                *(float4*)(myEa + 4 * (l + 16)) = gsrc[l + 16];
                *(float4*)(myEa + 4 * (l + 32)) = gsrc[l + 32];
            }
        }
        __syncwarp();

        // ---- phase A: m1, coalesced (4 consecutive edges x 8 lanes per pass) ----
#pragma unroll
        for (int it = 0; it < 8; it++) {
            const int e = 4 * it + er;
            const int de = __shfl_sync(0xffffffffu, dst, e);
            const int se = __shfl_sync(0xffffffffu, src, e);
            const bool ev = (e0 + e) < E;
            const float* par = Pab + (long long)de * 128;
            const float* pbr = Pab + (long long)se * 128 + 64;
#pragma unroll
            for (int h = 0; h < 2; h++) {
                const int c = c4 + 32 * h;
                float v0 = 0.f, v1 = 0.f, v2 = 0.f, v3 = 0.f;
                if (ev) {
                    float4 a = *(const float4*)(par + c);
                    float4 b = *(const float4*)(pbr + c);
                    v0 = a.x + b.x; v1 = a.y + b.y; v2 = a.z + b.z; v3 = a.w + b.w;
#pragma unroll
                    for (int q = 0; q < 6; q++) {
                        float  eq = myEa[e * 6 + q];
                        float4 wv = *(const float4*)(sW1c + q * 64 + c);
                        v0 = fmaf(eq, wv.x, v0);
                        v1 = fmaf(eq, wv.y, v1);
                        v2 = fmaf(eq, wv.z, v2);
                        v3 = fmaf(eq, wv.w, v3);
                    }
                }
                uint32_t r0 = f32_to_tf32(fmaxf(v0, 0.f));
                uint32_t r1 = f32_to_tf32(fmaxf(v1, 0.f));
                uint32_t r2 = f32_to_tf32(fmaxf(v2, 0.f));
                uint32_t r3 = f32_to_tf32(fmaxf(v3, 0.f));
                *(uint4*)(myA + e * A_STRIDE + c) = make_uint4(r0, r1, r2, r3);
            }
        }
        __syncwarp();

        // ---- mma: D(32x64) = m1 @ W2 ----
        float acc[2][8][4];
#pragma unroll
        for (int g = 0; g < 2; g++)
#pragma unroll
            for (int j = 0; j < 8; j++)
#pragma unroll
                for (int q = 0; q < 4; q++) acc[g][j][q] = 0.0f;

#pragma unroll
        for (int s = 0; s < 8; s++) {
            const int k0 = 8 * s;
            uint32_t bf[8][2];
#pragma unroll
            for (int j = 0; j < 8; j++) {
                bf[j][0] = sW2[(k0 + lt)     * W_STRIDE + 8 * j + lg];
                bf[j][1] = sW2[(k0 + lt + 4) * W_STRIDE + 8 * j + lg];
            }
            uint32_t af[2][4];
#pragma unroll
            for (int g = 0; g < 2; g++) {
                const uint32_t* base = myA + (16 * g + lg) * A_STRIDE + k0 + lt;
                af[g][0] = base[0];
                af[g][1] = base[8 * A_STRIDE];
                af[g][2] = base[4];
                af[g][3] = base[8 * A_STRIDE + 4];
            }
#pragma unroll
            for (int g = 0; g < 2; g++)
#pragma unroll
                for (int j = 0; j < 8; j++)
                    mma_tf32(acc[g][j], af[g], bf[j]);
        }
        __syncwarp();

        // ---- transpose to smem ----
#pragma unroll
        for (int g = 0; g < 2; g++)
#pragma unroll
            for (int h = 0; h < 2; h++) {
                const int row = 16 * g + 8 * h + lg;
#pragma unroll
                for (int j = 0; j < 8; j++)
                    *(float2*)(myF + row * A_STRIDE + 8 * j + 2 * lt) =
                        make_float2(acc[g][j][2 * h], acc[g][j][2 * h + 1]);
            }
        __syncwarp();

        // ---- segmented scan over sorted dst runs, RED only at tails ----
        {
            const int dprev = __shfl_up_sync(0xffffffffu, dst, 1);
            const int dnext = __shfl_down_sync(0xffffffffu, dst, 1);
            const bool head = (l == 0) || (dprev != dst);
            const bool tail = (l == 31) || (dnext != dst);
            const unsigned hm = __ballot_sync(0xffffffffu, head);
            const int hs = 31 - __clz(hm & lm_le);
            const int dist = l - hs;
            float* p = agg + (long long)dst * 64;
#pragma unroll
            for (int u = 0; u < 16; u++) {
                float4 t  = *(const float4*)(myF + l * A_STRIDE + 4 * u);
                float4 bb = *(const float4*)(sB2 + 4 * u);
                float x0 = 0.f, x1 = 0.f, x2 = 0.f, x3 = 0.f;
                if (valid) {
                    x0 = fmaxf(t.x + bb.x, 0.f);
                    x1 = fmaxf(t.y + bb.y, 0.f);
                    x2 = fmaxf(t.z + bb.z, 0.f);
                    x3 = fmaxf(t.w + bb.w, 0.f);
                }
#pragma unroll
                for (int s = 1; s < 32; s <<= 1) {
                    float y0 = __shfl_up_sync(0xffffffffu, x0, s);
                    float y1 = __shfl_up_sync(0xffffffffu, x1, s);
                    float y2 = __shfl_up_sync(0xffffffffu, x2, s);
                    float y3 = __shfl_up_sync(0xffffffffu, x3, s);
                    if (dist >= s) { x0 += y0; x1 += y1; x2 += y2; x3 += y3; }
                }
                if (tail && valid)
                    asm volatile("red.global.add.v4.f32 [%0], {%1, %2, %3, %4};"
                                 :: "l"(p + 4 * u), "f"(x0), "f"(x1), "f"(x2), "f"(x3)
                                 : "memory");
            }
        }
        __syncwarp();
    }
}

// ---------------- prediction head ---------------------------------------------
__global__ __launch_bounds__(256)
void pred_kernel(const float* __restrict__ h, const float* __restrict__ pw,
                 const float* __restrict__ pb, float* __restrict__ out, int M)
{
    __shared__ float spw[64];
    __shared__ float swarp[8];
    if (threadIdx.x < 64) spw[threadIdx.x] = pw[threadIdx.x];
    __syncthreads();

    float sum = 0.0f;
    for (long long row = (long long)blockIdx.x * blockDim.x + threadIdx.x; row < M;
         row += (long long)gridDim.x * blockDim.x) {
        const float4* hr = (const float4*)(h + row * 64);
#pragma unroll
        for (int u = 0; u < 16; u++) {
            float4 v = hr[u];
            sum = fmaf(v.x, spw[4 * u + 0], sum);
            sum = fmaf(v.y, spw[4 * u + 1], sum);
            sum = fmaf(v.z, spw[4 * u + 2], sum);
            sum = fmaf(v.w, spw[4 * u + 3], sum);
        }
    }
#pragma unroll
    for (int o = 16; o > 0; o >>= 1) sum += __shfl_down_sync(0xffffffffu, sum, o);
    if ((threadIdx.x & 31) == 0) swarp[threadIdx.x >> 5] = sum;
    __syncthreads();
    if (threadIdx.x < 8) {
        float s = swarp[threadIdx.x];
#pragma unroll
        for (int o = 4; o > 0; o >>= 1) s += __shfl_down_sync(0xffu, s, o);
        if (threadIdx.x == 0) {
            if (blockIdx.x == 0) s = fmaf(pb[0], (float)M, s);
            atomicAdd(out, s);
        }
    }
}

// ---------------- launch ------------------------------------------------------
extern "C" void kernel_launch(void* const* d_in, const int* in_sizes, int n_in,
                              void* d_out, int out_size)
{
    const float* x       = (const float*)d_in[0];
    const void*  ei      = d_in[1];
    const float* eattr   = (const float*)d_in[2];
    const float* lin_w   = (const float*)d_in[3];
    const float* lin_b   = (const float*)d_in[4];
    const float* msg_w1  = (const float*)d_in[5];
    const float* msg_b1  = (const float*)d_in[6];
    const float* msg_w2  = (const float*)d_in[7];
    const float* msg_b2  = (const float*)d_in[8];
    const float* upd_w1  = (const float*)d_in[9];
    const float* upd_b1  = (const float*)d_in[10];
    const float* upd_w2  = (const float*)d_in[11];
    const float* upd_b2  = (const float*)d_in[12];
    const float* pred_w  = (const float*)d_in[13];
    const float* pred_b  = (const float*)d_in[14];

    const int M = in_sizes[0] / 128;   // 50000
    const int E = in_sizes[2] / 6;     // 800000

    float *h, *Pab, *agg;
    int* cnt;
    cudaGetSymbolAddress((void**)&h,   g_h);
    cudaGetSymbolAddress((void**)&Pab, g_Pab);
    cudaGetSymbolAddress((void**)&agg, g_agg);
    cudaGetSymbolAddress((void**)&cnt, g_cnt);

    const int gN = (M + 63) / 64;
    const int DSMEM = 96000;
    cudaFuncSetAttribute(edge_kernel_mma,
                         cudaFuncAttributeMaxDynamicSharedMemorySize, DSMEM);
    const int nChunks = (E + 31) / 32;
    int gEdge = 148 * 2;
    if (gEdge * 8 > nChunks) gEdge = (nChunks + 7) / 8;
    if (gEdge < 1) gEdge = 1;

    // ---- sort edges by dst (once; reused by all 4 layers) ----
    detect_idx_kernel<<<1, 32>>>((const unsigned int*)ei);
    cudaMemsetAsync(cnt, 0, NSCAN * sizeof(int));
    hist_kernel<<<1024, 256>>>(ei, E);
    scan1_kernel<<<NSCAN / 1024, 1024>>>();
    scan2_kernel<<<1, 32>>>(NSCAN / 1024);
    scan3_kernel<<<NSCAN / 1024, 1024>>>();
    scatter_kernel<<<1024, 256>>>(ei, eattr, E);

    // input projection
    node_gemm64<false><<<gN, 256>>>(x, lin_w, 128, lin_b, h, M);

    for (int l = 0; l < 4; l++) {
        const float* W1 = msg_w1 + (size_t)l * 134 * 64;
        node_gemm_dual<<<gN, 512>>>(h, W1, msg_b1 + l * 64, Pab, M);
        edge_kernel_mma<<<gEdge, 256, DSMEM>>>(Pab,
                                               W1 + 128 * 64,
                                               msg_w2 + (size_t)l * 64 * 64,
                                               msg_b2 + l * 64, agg, E);
        fused_update<<<gN, 256>>>(h, upd_w1 + (size_t)l * 128 * 64,
                                  upd_b1 + l * 64,
                                  upd_w2 + (size_t)l * 64 * 64,
                                  upd_b2 + l * 64, agg, h, M);
    }

    cudaMemsetAsync(d_out, 0, sizeof(float));
    pred_kernel<<<256, 256>>>(h, pred_w, pred_b, (float*)d_out, M);
}